// round 13
// baseline (speedup 1.0000x reference)
#include <cuda_runtime.h>
#include <cstdint>

#define BB 256
#define TT 2048
#define II 64
#define HH 256

// Persistent scratch for the input projection (zero-init; t>=len never written).
__device__ float g_xp[(size_t)BB * TT * HH];

typedef unsigned long long u64;

__device__ __forceinline__ u64 pack2(float lo, float hi) {
    u64 r; asm("mov.b64 %0, {%1,%2};" : "=l"(r) : "f"(lo), "f"(hi)); return r;
}
__device__ __forceinline__ u64 dup2(float v) {
    u64 r; asm("mov.b64 %0, {%1,%1};" : "=l"(r) : "f"(v)); return r;
}
__device__ __forceinline__ void ffma2(u64& acc, u64 a, u64 b) {
    asm("fma.rn.f32x2 %0, %1, %2, %0;" : "+l"(acc) : "l"(a), "l"(b));
}
__device__ __forceinline__ u64 add2(u64 a, u64 b) {
    u64 r; asm("add.rn.f32x2 %0, %1, %2;" : "=l"(r) : "l"(a), "l"(b)); return r;
}
__device__ __forceinline__ float2 unpack2(u64 v) {
    float2 f; asm("mov.b64 {%0,%1}, %2;" : "=f"(f.x), "=f"(f.y) : "l"(v)); return f;
}
__device__ __forceinline__ float tanhap(float x) {
    float y; asm("tanh.approx.f32 %0, %1;" : "=f"(y) : "f"(x)); return y;
}
__device__ __forceinline__ u64 shfl64(u64 v, int mask) {
    return __shfl_xor_sync(0xffffffffu, v, mask);
}

// ---------------------------------------------------------------------------
// Kernel A: xp[b,t,h] = sum_i x[b,t,i]*W_ih[h,i] + b_ih[h] + b_hh[h], t < len[b]
// ---------------------------------------------------------------------------
__global__ __launch_bounds__(256) void xproj_kernel(
    const float* __restrict__ x,
    const int*   __restrict__ lengths,
    const float* __restrict__ W_ih,
    const float* __restrict__ b_ih,
    const float* __restrict__ b_hh)
{
    extern __shared__ float sm[];
    float* ws = sm;                 // [256][65]
    float* xs = sm + 256 * 65;      // [64][64]

    const int b  = blockIdx.y;
    const int t0 = blockIdx.x * 64;
    const int len = lengths[b];
    if (t0 >= len) return;
    const int tcnt = min(64, len - t0);
    const int tid = threadIdx.x;

    for (int idx = tid; idx < HH * II; idx += 256) {
        int h = idx >> 6, i = idx & 63;
        ws[h * 65 + i] = W_ih[idx];
    }
    const float* xbase = x + ((size_t)b * TT + t0) * II;
    for (int idx = tid; idx < tcnt * II; idx += 256) {
        xs[idx] = xbase[idx];
    }
    __syncthreads();

    const int h = tid;
    u64 wp[II / 2];
#pragma unroll
    for (int q = 0; q < II / 2; q++)
        wp[q] = pack2(ws[h * 65 + 2 * q], ws[h * 65 + 2 * q + 1]);
    const u64 bias0 = pack2(b_ih[h] + b_hh[h], 0.f);

    float* xpb = g_xp + ((size_t)b * TT + t0) * HH + h;

    for (int tt = 0; tt < tcnt; tt++) {
        u64 acc0 = bias0, acc1 = 0ull;
        const ulonglong2* xr = (const ulonglong2*)(xs + tt * II);
#pragma unroll
        for (int q = 0; q < II / 4; q++) {
            ulonglong2 xv = xr[q];
            ffma2(acc0, wp[2 * q],     xv.x);
            ffma2(acc1, wp[2 * q + 1], xv.y);
        }
        float2 f0 = unpack2(acc0), f1 = unpack2(acc1);
        xpb[(size_t)tt * HH] = (f0.x + f0.y) + (f1.x + f1.y);
    }
}

// ---------------------------------------------------------------------------
// Kernel B: persistent scan = round-2 inner loop (best measured) + short tail.
// 128 CTAs x 256 threads, 2 batch rows/CTA.
// Thread (g=tid>>2, c=tid&3): owns j-quad [4g,4g+4), k ≡ c (mod 4).
// W^T rows k<KSM in smem fp32 (stride RS=264 -> conflict-free LDS.128);
// rows k>=KSM packed in registers as f32x2 pairs. h as float2 (h_b0,h_b1).
// Tail: 2-level u64 reduce-scatter (3 shfl64) -> lane c holds full sums for
// j-pair jp=4g+2(c&1), batch b0+(c>>1); tanh.approx; shfl64 batch-exchange;
// even lanes store one STS.128 into hnxt.
// ---------------------------------------------------------------------------
#define RS 264
#define KSM 80
#define SMI (KSM / 4)            // 20 smem k-iterations
#define RGI ((HH - KSM) / 4)     // 44 register k-iterations

__global__ __launch_bounds__(256, 1) void scan_kernel(
    const float* __restrict__ W_hh,
    const int*   __restrict__ lengths,
    const float* __restrict__ W_fc,
    const float* __restrict__ b_fc,
    float*       __restrict__ out)
{
    extern __shared__ float sm[];
    float*  WT_s = sm;                          // [KSM][RS]
    float2* hb0  = (float2*)(sm + KSM * RS);    // [256] (h_b0, h_b1)
    float2* hb1  = hb0 + HH;                    // [256]
    float*  hlast = (float*)(hb1 + HH);         // [2][256]
    float*  red   = hlast + 2 * HH;             // [16]

    const int tid = threadIdx.x;
    const int c = tid & 3;
    const int g = tid >> 2;
    const int b0 = blockIdx.x * 2, b1 = b0 + 1;
    const int L0 = lengths[b0], L1 = lengths[b1];
    const int Tmax = max(L0, L1);

    // Stage W^T rows k < KSM into smem (coalesced read of W_hh).
    for (int idx = tid; idx < HH * HH; idx += 256) {
        int j = idx >> 8, k = idx & 255;
        float v = W_hh[idx];
        if (k < KSM) WT_s[k * RS + j] = v;
    }
    // Register-resident packed W pairs for k in [KSM, 256).
    u64 wpA[RGI], wpB[RGI];
#pragma unroll
    for (int ii = 0; ii < RGI; ii++) {
        int k = KSM + 4 * ii + c;
        wpA[ii] = pack2(__ldg(&W_hh[(4 * g + 0) * HH + k]),
                        __ldg(&W_hh[(4 * g + 1) * HH + k]));
        wpB[ii] = pack2(__ldg(&W_hh[(4 * g + 2) * HH + k]),
                        __ldg(&W_hh[(4 * g + 3) * HH + k]));
    }
    hb0[tid] = make_float2(0.f, 0.f);
    hlast[tid] = 0.f; hlast[HH + tid] = 0.f;
    __syncthreads();

    // Per-lane tail mapping: batch bsel = b0 + (c>>1), j-pair jp = 4g + 2*(c&1).
    const int  bsh  = c >> 1;
    const int  jp   = 4 * g + 2 * (c & 1);
    const int  Lsel = bsh ? L1 : L0;
    const float2* px = (const float2*)(g_xp + (size_t)(b0 + bsh) * TT * HH + jp);

    const unsigned base_s = c * RS + 4 * g;
    float2 xq = px[0];                      // xp for t = 0

    for (int t = 0; t < Tmax; t++) {
        const float2* hcur = (t & 1) ? hb1 : hb0;
        float2*       hnxt = (t & 1) ? hb0 : hb1;

        // prefetch xp for t+1 (consumed next iteration)
        int tn = min(t + 1, Tmax - 1);
        float2 xq_next = px[(size_t)tn * (HH / 2)];

        u64 aA = 0ull, aB = 0ull;   // batch b0: (j0,j1),(j2,j3)
        u64 cA = 0ull, cB = 0ull;   // batch b1

#pragma unroll
        for (int i = 0; i < SMI; i++) {
            ulonglong2 wv = *(const ulonglong2*)&WT_s[base_s + (unsigned)(4 * i) * RS];
            float2 hv = hcur[4 * i + c];
            u64 d0 = dup2(hv.x), d1 = dup2(hv.y);
            ffma2(aA, wv.x, d0); ffma2(aB, wv.y, d0);
            ffma2(cA, wv.x, d1); ffma2(cB, wv.y, d1);
        }
#pragma unroll
        for (int ii = 0; ii < RGI; ii++) {
            float2 hv = hcur[KSM + 4 * ii + c];
            u64 d0 = dup2(hv.x), d1 = dup2(hv.y);
            ffma2(aA, wpA[ii], d0); ffma2(aB, wpB[ii], d0);
            ffma2(cA, wpA[ii], d1); ffma2(cB, wpB[ii], d1);
        }

        // 2-level u64 reduce-scatter over the 4 k-split lanes.
        // Level mask 2 (batch split): lane keeps its final batch's items.
        const bool hi2 = (c & 2) != 0;
        u64 keepA = hi2 ? cA : aA,  sendA = hi2 ? aA : cA;
        u64 keepB = hi2 ? cB : aB,  sendB = hi2 ? aB : cB;
        u64 PA = add2(keepA, shfl64(sendA, 2));
        u64 PB = add2(keepB, shfl64(sendB, 2));
        // Level mask 1 (j-pair split).
        const bool hi1 = (c & 1) != 0;
        u64 keepF = hi1 ? PB : PA,  sendF = hi1 ? PA : PB;
        u64 F = add2(keepF, shfl64(sendF, 1));

        float2 f = unpack2(F);
        float v0 = tanhap(f.x + xq.x);      // h_{bsel}[jp]
        float v1 = tanhap(f.y + xq.y);      // h_{bsel}[jp+1]

        // Exchange with batch-partner (lane c^2) and have even-batch lanes
        // store both batches' values for (jp, jp+1) as one STS.128.
        u64 V = pack2(v0, v1);
        u64 R = shfl64(V, 2);               // other batch, same j-pair
        if (!hi2) {
            float2 r = unpack2(R);
            *(float4*)&hnxt[jp] = make_float4(v0, r.x, v1, r.y);
        }

        if (t == Lsel - 1)
            *(float2*)&hlast[bsh * HH + jp] = make_float2(v0, v1);

        xq = xq_next;
        __syncthreads();   // hnxt visible; fences next-iter writes vs reads
    }

    // Final FC: out[b] = dot(hlast[b], W_fc) + b_fc
    float wf = W_fc[tid];
#pragma unroll
    for (int bb = 0; bb < 2; bb++) {
        float v = hlast[bb * HH + tid] * wf;
#pragma unroll
        for (int o = 16; o > 0; o >>= 1) v += __shfl_down_sync(0xffffffffu, v, o);
        if ((tid & 31) == 0) red[bb * 8 + (tid >> 5)] = v;
    }
    __syncthreads();
    if (tid < 2) {
        float s = b_fc[0];
#pragma unroll
        for (int q = 0; q < 8; q++) s += red[tid * 8 + q];
        out[b0 + tid] = s;
    }
}

// ---------------------------------------------------------------------------
extern "C" void kernel_launch(void* const* d_in, const int* in_sizes, int n_in,
                              void* d_out, int out_size)
{
    const float* x     = (const float*)d_in[0];
    const int*   lens  = (const int*)  d_in[1];
    const float* W_ih  = (const float*)d_in[2];
    const float* W_hh  = (const float*)d_in[3];
    const float* b_ih  = (const float*)d_in[4];
    const float* b_hh  = (const float*)d_in[5];
    const float* W_fc  = (const float*)d_in[6];
    const float* b_fc  = (const float*)d_in[7];
    float* out = (float*)d_out;

    const int A_SMEM = (256 * 65 + 64 * 64) * 4;                        // 82944 B
    const int B_SMEM = (KSM * RS + 2 * HH * 2 + 2 * HH + 16) * 4;       // ~91 KB
    cudaFuncSetAttribute(xproj_kernel, cudaFuncAttributeMaxDynamicSharedMemorySize, A_SMEM);
    cudaFuncSetAttribute(scan_kernel,  cudaFuncAttributeMaxDynamicSharedMemorySize, B_SMEM);

    dim3 gA(TT / 64, BB);
    xproj_kernel<<<gA, 256, A_SMEM>>>(x, lens, W_ih, b_ih, b_hh);
    scan_kernel<<<BB / 2, 256, B_SMEM>>>(W_hh, lens, W_fc, b_fc, out);
}

// round 14
// speedup vs baseline: 1.0023x; 1.0023x over previous
#include <cuda_runtime.h>
#include <cstdint>

#define BB 256
#define TT 2048
#define II 64
#define HH 256

// Persistent scratch for the input projection (zero-init; t>=len never written).
__device__ float g_xp[(size_t)BB * TT * HH];

typedef unsigned long long u64;

__device__ __forceinline__ u64 pack2(float lo, float hi) {
    u64 r; asm("mov.b64 %0, {%1,%2};" : "=l"(r) : "f"(lo), "f"(hi)); return r;
}
__device__ __forceinline__ u64 dup2(float v) {
    u64 r; asm("mov.b64 %0, {%1,%1};" : "=l"(r) : "f"(v)); return r;
}
__device__ __forceinline__ void ffma2(u64& acc, u64 a, u64 b) {
    asm("fma.rn.f32x2 %0, %1, %2, %0;" : "+l"(acc) : "l"(a), "l"(b));
}
__device__ __forceinline__ u64 add2(u64 a, u64 b) {
    u64 r; asm("add.rn.f32x2 %0, %1, %2;" : "=l"(r) : "l"(a), "l"(b)); return r;
}
__device__ __forceinline__ float2 unpack2(u64 v) {
    float2 f; asm("mov.b64 {%0,%1}, %2;" : "=f"(f.x), "=f"(f.y) : "l"(v)); return f;
}
__device__ __forceinline__ float tanhap(float x) {
    float y; asm("tanh.approx.f32 %0, %1;" : "=f"(y) : "f"(x)); return y;
}
__device__ __forceinline__ u64 shfl64(u64 v, int mask) {
    return __shfl_xor_sync(0xffffffffu, v, mask);
}

// ---------------------------------------------------------------------------
// Kernel A: xp[b,t,h] = sum_i x[b,t,i]*W_ih[h,i] + b_ih[h] + b_hh[h], t < len[b]
// ---------------------------------------------------------------------------
__global__ __launch_bounds__(256) void xproj_kernel(
    const float* __restrict__ x,
    const int*   __restrict__ lengths,
    const float* __restrict__ W_ih,
    const float* __restrict__ b_ih,
    const float* __restrict__ b_hh)
{
    extern __shared__ float sm[];
    float* ws = sm;                 // [256][65]
    float* xs = sm + 256 * 65;      // [64][64]

    const int b  = blockIdx.y;
    const int t0 = blockIdx.x * 64;
    const int len = lengths[b];
    if (t0 >= len) return;
    const int tcnt = min(64, len - t0);
    const int tid = threadIdx.x;

    for (int idx = tid; idx < HH * II; idx += 256) {
        int h = idx >> 6, i = idx & 63;
        ws[h * 65 + i] = W_ih[idx];
    }
    const float* xbase = x + ((size_t)b * TT + t0) * II;
    for (int idx = tid; idx < tcnt * II; idx += 256) {
        xs[idx] = xbase[idx];
    }
    __syncthreads();

    const int h = tid;
    u64 wp[II / 2];
#pragma unroll
    for (int q = 0; q < II / 2; q++)
        wp[q] = pack2(ws[h * 65 + 2 * q], ws[h * 65 + 2 * q + 1]);
    const u64 bias0 = pack2(b_ih[h] + b_hh[h], 0.f);

    float* xpb = g_xp + ((size_t)b * TT + t0) * HH + h;

    for (int tt = 0; tt < tcnt; tt++) {
        u64 acc0 = bias0, acc1 = 0ull;
        const ulonglong2* xr = (const ulonglong2*)(xs + tt * II);
#pragma unroll
        for (int q = 0; q < II / 4; q++) {
            ulonglong2 xv = xr[q];
            ffma2(acc0, wp[2 * q],     xv.x);
            ffma2(acc1, wp[2 * q + 1], xv.y);
        }
        float2 f0 = unpack2(acc0), f1 = unpack2(acc1);
        xpb[(size_t)tt * HH] = (f0.x + f0.y) + (f1.x + f1.y);
    }
}

// ---------------------------------------------------------------------------
// Kernel B: persistent scan = round-2 inner loop (best measured) + short tail.
// 128 CTAs x 256 threads, 2 batch rows/CTA.
// Thread (g=tid>>2, c=tid&3): owns j-quad [4g,4g+4), k ≡ c (mod 4).
// W^T rows k<KSM in smem fp32 (stride RS=264 -> conflict-free LDS.128);
// rows k>=KSM packed in registers as f32x2 pairs. h as float2 (h_b0,h_b1).
// Tail: 2-level u64 reduce-scatter (3 shfl64) -> lane c holds full sums for
// j-pair jp=4g+2(c&1), batch b0+(c>>1); tanh.approx; shfl64 batch-exchange;
// even lanes store one STS.128 into hnxt.
// ---------------------------------------------------------------------------
#define RS 264
#define KSM 80
#define SMI (KSM / 4)            // 20 smem k-iterations
#define RGI ((HH - KSM) / 4)     // 44 register k-iterations

__global__ __launch_bounds__(256, 1) void scan_kernel(
    const float* __restrict__ W_hh,
    const int*   __restrict__ lengths,
    const float* __restrict__ W_fc,
    const float* __restrict__ b_fc,
    float*       __restrict__ out)
{
    extern __shared__ float sm[];
    float*  WT_s = sm;                          // [KSM][RS]
    float2* hb0  = (float2*)(sm + KSM * RS);    // [256] (h_b0, h_b1)
    float2* hb1  = hb0 + HH;                    // [256]
    float*  hlast = (float*)(hb1 + HH);         // [2][256]
    float*  red   = hlast + 2 * HH;             // [16]

    const int tid = threadIdx.x;
    const int c = tid & 3;
    const int g = tid >> 2;
    const int b0 = blockIdx.x * 2, b1 = b0 + 1;
    const int L0 = lengths[b0], L1 = lengths[b1];
    const int Tmax = max(L0, L1);

    // Stage W^T rows k < KSM into smem (coalesced read of W_hh).
    for (int idx = tid; idx < HH * HH; idx += 256) {
        int j = idx >> 8, k = idx & 255;
        float v = W_hh[idx];
        if (k < KSM) WT_s[k * RS + j] = v;
    }
    // Register-resident packed W pairs for k in [KSM, 256).
    u64 wpA[RGI], wpB[RGI];
#pragma unroll
    for (int ii = 0; ii < RGI; ii++) {
        int k = KSM + 4 * ii + c;
        wpA[ii] = pack2(__ldg(&W_hh[(4 * g + 0) * HH + k]),
                        __ldg(&W_hh[(4 * g + 1) * HH + k]));
        wpB[ii] = pack2(__ldg(&W_hh[(4 * g + 2) * HH + k]),
                        __ldg(&W_hh[(4 * g + 3) * HH + k]));
    }
    hb0[tid] = make_float2(0.f, 0.f);
    hlast[tid] = 0.f; hlast[HH + tid] = 0.f;
    __syncthreads();

    // Per-lane tail mapping: batch bsel = b0 + (c>>1), j-pair jp = 4g + 2*(c&1).
    const int  bsh  = c >> 1;
    const int  jp   = 4 * g + 2 * (c & 1);
    const int  Lsel = bsh ? L1 : L0;
    const float2* px = (const float2*)(g_xp + (size_t)(b0 + bsh) * TT * HH + jp);

    const unsigned base_s = c * RS + 4 * g;
    float2 xq = px[0];                      // xp for t = 0

    for (int t = 0; t < Tmax; t++) {
        const float2* hcur = (t & 1) ? hb1 : hb0;
        float2*       hnxt = (t & 1) ? hb0 : hb1;

        // prefetch xp for t+1 (consumed next iteration)
        int tn = min(t + 1, Tmax - 1);
        float2 xq_next = px[(size_t)tn * (HH / 2)];

        u64 aA = 0ull, aB = 0ull;   // batch b0: (j0,j1),(j2,j3)
        u64 cA = 0ull, cB = 0ull;   // batch b1

#pragma unroll
        for (int i = 0; i < SMI; i++) {
            ulonglong2 wv = *(const ulonglong2*)&WT_s[base_s + (unsigned)(4 * i) * RS];
            float2 hv = hcur[4 * i + c];
            u64 d0 = dup2(hv.x), d1 = dup2(hv.y);
            ffma2(aA, wv.x, d0); ffma2(aB, wv.y, d0);
            ffma2(cA, wv.x, d1); ffma2(cB, wv.y, d1);
        }
#pragma unroll
        for (int ii = 0; ii < RGI; ii++) {
            float2 hv = hcur[KSM + 4 * ii + c];
            u64 d0 = dup2(hv.x), d1 = dup2(hv.y);
            ffma2(aA, wpA[ii], d0); ffma2(aB, wpB[ii], d0);
            ffma2(cA, wpA[ii], d1); ffma2(cB, wpB[ii], d1);
        }

        // 2-level u64 reduce-scatter over the 4 k-split lanes.
        // Level mask 2 (batch split): lane keeps its final batch's items.
        const bool hi2 = (c & 2) != 0;
        u64 keepA = hi2 ? cA : aA,  sendA = hi2 ? aA : cA;
        u64 keepB = hi2 ? cB : aB,  sendB = hi2 ? aB : cB;
        u64 PA = add2(keepA, shfl64(sendA, 2));
        u64 PB = add2(keepB, shfl64(sendB, 2));
        // Level mask 1 (j-pair split).
        const bool hi1 = (c & 1) != 0;
        u64 keepF = hi1 ? PB : PA,  sendF = hi1 ? PA : PB;
        u64 F = add2(keepF, shfl64(sendF, 1));

        float2 f = unpack2(F);
        float v0 = tanhap(f.x + xq.x);      // h_{bsel}[jp]
        float v1 = tanhap(f.y + xq.y);      // h_{bsel}[jp+1]

        // Exchange with batch-partner (lane c^2) and have even-batch lanes
        // store both batches' values for (jp, jp+1) as one STS.128.
        u64 V = pack2(v0, v1);
        u64 R = shfl64(V, 2);               // other batch, same j-pair
        if (!hi2) {
            float2 r = unpack2(R);
            *(float4*)&hnxt[jp] = make_float4(v0, r.x, v1, r.y);
        }

        if (t == Lsel - 1)
            *(float2*)&hlast[bsh * HH + jp] = make_float2(v0, v1);

        xq = xq_next;
        __syncthreads();   // hnxt visible; fences next-iter writes vs reads
    }

    // Final FC: out[b] = dot(hlast[b], W_fc) + b_fc
    float wf = W_fc[tid];
#pragma unroll
    for (int bb = 0; bb < 2; bb++) {
        float v = hlast[bb * HH + tid] * wf;
#pragma unroll
        for (int o = 16; o > 0; o >>= 1) v += __shfl_down_sync(0xffffffffu, v, o);
        if ((tid & 31) == 0) red[bb * 8 + (tid >> 5)] = v;
    }
    __syncthreads();
    if (tid < 2) {
        float s = b_fc[0];
#pragma unroll
        for (int q = 0; q < 8; q++) s += red[tid * 8 + q];
        out[b0 + tid] = s;
    }
}

// ---------------------------------------------------------------------------
extern "C" void kernel_launch(void* const* d_in, const int* in_sizes, int n_in,
                              void* d_out, int out_size)
{
    const float* x     = (const float*)d_in[0];
    const int*   lens  = (const int*)  d_in[1];
    const float* W_ih  = (const float*)d_in[2];
    const float* W_hh  = (const float*)d_in[3];
    const float* b_ih  = (const float*)d_in[4];
    const float* b_hh  = (const float*)d_in[5];
    const float* W_fc  = (const float*)d_in[6];
    const float* b_fc  = (const float*)d_in[7];
    float* out = (float*)d_out;

    const int A_SMEM = (256 * 65 + 64 * 64) * 4;                        // 82944 B
    const int B_SMEM = (KSM * RS + 2 * HH * 2 + 2 * HH + 16) * 4;       // ~91 KB
    cudaFuncSetAttribute(xproj_kernel, cudaFuncAttributeMaxDynamicSharedMemorySize, A_SMEM);
    cudaFuncSetAttribute(scan_kernel,  cudaFuncAttributeMaxDynamicSharedMemorySize, B_SMEM);

    dim3 gA(TT / 64, BB);
    xproj_kernel<<<gA, 256, A_SMEM>>>(x, lens, W_ih, b_ih, b_hh);
    scan_kernel<<<BB / 2, 256, B_SMEM>>>(W_hh, lens, W_fc, b_fc, out);
}